// round 1
// baseline (speedup 1.0000x reference)
#include <cuda_runtime.h>
#include <cuda_bf16.h>

// Problem constants (fixed by the reference generator)
#define NN 10000     // nodes
#define NE 4000      // edges
#define INCH 128
#define OUTCH 64
#define HO 128       // HEADS*OUT_CH

#define MAXM (4 * 1024 * 1024)  // max total incidence entries across both scales

// ---------------- device scratch (no allocations allowed) ----------------
__device__ float g_VT[128 * 128];       // folded weights, stored transposed: VT[k*128 + j]
__device__ float g_cc[128];             // folded biases (scale0 cols 0..63, scale1 cols 64..127)
__device__ float g_Y[NN * 128];         // Y = x @ Vcat^T + ccat
__device__ float g_emean[2 * NE * 64];  // per-(scale,edge) mean, 64 channels
__device__ int g_ecnt[2 * NE + 1], g_eptr[2 * NE + 1], g_epos[2 * NE];
__device__ int g_ncnt[NN + 1], g_nptr[NN + 1], g_npos[NN];
__device__ int g_emem[MAXM];            // CSR by edge-slot: member node ids
__device__ int g_nmem[MAXM];            // CSR by node: member edge-slot ids

// ---------------- kernel: zero the histograms ----------------
__global__ void zero_kernel() {
    int i = blockIdx.x * blockDim.x + threadIdx.x;
    if (i < 2 * NE) g_ecnt[i] = 0;
    if (i < NN) g_ncnt[i] = 0;
}

// ---------------- kernel: fold Wout into W1/W2, b1/b2 ----------------
// VT[k*128 + j] = sum_h Wout[jo][h] * Ws[h][k],   j = s*64 + jo
__global__ void fold_kernel(const float* __restrict__ W1, const float* __restrict__ b1,
                            const float* __restrict__ W2, const float* __restrict__ b2,
                            const float* __restrict__ Wout) {
    if (blockIdx.x < 64) {
        int idx = blockIdx.x * 256 + threadIdx.x;  // [0, 16384)
        int j = idx >> 7, k = idx & 127;
        int s = j >> 6, jo = j & 63;
        const float* W = s ? W2 : W1;
        float sum = 0.f;
#pragma unroll 8
        for (int h = 0; h < 128; h++) sum = fmaf(Wout[jo * 128 + h], W[h * 128 + k], sum);
        g_VT[k * 128 + j] = sum;
    } else {
        int j = threadIdx.x;
        if (j < 128) {
            int s = j >> 6, jo = j & 63;
            const float* b = s ? b2 : b1;
            float sum = 0.f;
#pragma unroll 8
            for (int h = 0; h < 128; h++) sum = fmaf(Wout[jo * 128 + h], b[h], sum);
            g_cc[j] = sum;
        }
    }
}

// ---------------- kernel: histogram of edge slots and nodes ----------------
__global__ void hist_kernel(const int* __restrict__ hi1, const int* __restrict__ hi2,
                            int nnz1, int nnz2) {
    int k = blockIdx.x * blockDim.x + threadIdx.x;
    int tot = nnz1 + nnz2;
    if (k >= tot) return;
    int node, slot;
    if (k < nnz1) { node = hi1[k]; slot = hi1[nnz1 + k]; }
    else { int kk = k - nnz1; node = hi2[kk]; slot = NE + hi2[nnz2 + kk]; }
    atomicAdd(&g_ecnt[slot], 1);
    atomicAdd(&g_ncnt[node], 1);
}

// ---------------- kernel: exclusive scan (block 0 = edge slots, block 1 = nodes) ----------------
__global__ void scan_kernel() {
    __shared__ int s[1024];
    int n;
    int *cnt, *ptr, *pos;
    if (blockIdx.x == 0) { n = 2 * NE; cnt = g_ecnt; ptr = g_eptr; pos = g_epos; }
    else { n = NN; cnt = g_ncnt; ptr = g_nptr; pos = g_npos; }
    int t = threadIdx.x;
    int carry = 0;
    for (int base = 0; base < n; base += 1024) {
        int i = base + t;
        int v = (i < n) ? cnt[i] : 0;
        int x = v;
        s[t] = v;
        __syncthreads();
        for (int off = 1; off < 1024; off <<= 1) {
            int w = (t >= off) ? s[t - off] : 0;
            __syncthreads();
            x += w;
            s[t] = x;
            __syncthreads();
        }
        if (i < n) { ptr[i] = carry + x - v; pos[i] = carry + x - v; }
        int tot = s[1023];
        __syncthreads();
        carry += tot;
    }
    if (t == 0) ptr[n] = carry;
}

// ---------------- kernel: fill CSR member arrays ----------------
__global__ void fill_kernel(const int* __restrict__ hi1, const int* __restrict__ hi2,
                            int nnz1, int nnz2) {
    int k = blockIdx.x * blockDim.x + threadIdx.x;
    int tot = nnz1 + nnz2;
    if (k >= tot) return;
    int node, slot;
    if (k < nnz1) { node = hi1[k]; slot = hi1[nnz1 + k]; }
    else { int kk = k - nnz1; node = hi2[kk]; slot = NE + hi2[nnz2 + kk]; }
    int p = atomicAdd(&g_epos[slot], 1);
    g_emem[p] = node;
    int q = atomicAdd(&g_npos[node], 1);
    g_nmem[q] = slot;
}

// ---------------- kernel: Y = x @ Vcat^T + ccat ----------------
// blockDim = 128. Block computes 64 rows x 128 cols. Thread: 16 rows x 4 cols.
#define FMA4(a, sc, v)                 \
    a.x = fmaf(sc, v.x, a.x);          \
    a.y = fmaf(sc, v.y, a.y);          \
    a.z = fmaf(sc, v.z, a.z);          \
    a.w = fmaf(sc, v.w, a.w);

__global__ __launch_bounds__(128) void gemm_kernel(const float* __restrict__ x) {
    int tx = threadIdx.x & 31;   // 4-col group: cols tx*4 .. tx*4+3
    int ty = threadIdx.x >> 5;   // row group: 16 rows
    int row0 = blockIdx.x * 64 + ty * 16;
    const float4* x4 = (const float4*)x;
    const float4* v4 = (const float4*)g_VT;

    int rbase[16];
#pragma unroll
    for (int r = 0; r < 16; r++) {
        int row = row0 + r;
        rbase[r] = (row < NN ? row : NN - 1) * 32;
    }
    float4 acc[16];
#pragma unroll
    for (int r = 0; r < 16; r++) acc[r] = make_float4(0.f, 0.f, 0.f, 0.f);

#pragma unroll 2
    for (int k4 = 0; k4 < 32; k4++) {
        float4 v0 = v4[(4 * k4 + 0) * 32 + tx];
        float4 v1 = v4[(4 * k4 + 1) * 32 + tx];
        float4 v2 = v4[(4 * k4 + 2) * 32 + tx];
        float4 v3 = v4[(4 * k4 + 3) * 32 + tx];
#pragma unroll
        for (int r = 0; r < 16; r++) {
            float4 xq = x4[rbase[r] + k4];
            FMA4(acc[r], xq.x, v0);
            FMA4(acc[r], xq.y, v1);
            FMA4(acc[r], xq.z, v2);
            FMA4(acc[r], xq.w, v3);
        }
    }
    float4 c = ((const float4*)g_cc)[tx];
#pragma unroll
    for (int r = 0; r < 16; r++) {
        int row = row0 + r;
        if (row < NN) {
            float4 o = acc[r];
            o.x += c.x; o.y += c.y; o.z += c.z; o.w += c.w;
            ((float4*)g_Y)[row * 32 + tx] = o;
        }
    }
}

// ---------------- kernel: per-edge-slot mean (warp per slot) ----------------
__global__ void edge_mean_kernel() {
    int w = (blockIdx.x * 256 + threadIdx.x) >> 5;
    int lane = threadIdx.x & 31;
    if (w >= 2 * NE) return;
    int beg = g_eptr[w], end = g_eptr[w + 1];
    int col = ((w >= NE) ? 32 : 0) + lane;  // float2 column within the 64-float2 row of Y
    const float2* Y2 = (const float2*)g_Y;
    float sx = 0.f, sy = 0.f;
    int j = beg;
    for (; j + 4 <= end; j += 4) {
        int n0 = g_emem[j], n1 = g_emem[j + 1], n2 = g_emem[j + 2], n3 = g_emem[j + 3];
        float2 a = Y2[n0 * 64 + col];
        float2 b = Y2[n1 * 64 + col];
        float2 c = Y2[n2 * 64 + col];
        float2 d = Y2[n3 * 64 + col];
        sx += (a.x + b.x) + (c.x + d.x);
        sy += (a.y + b.y) + (c.y + d.y);
    }
    for (; j < end; j++) {
        int n0 = g_emem[j];
        float2 a = Y2[n0 * 64 + col];
        sx += a.x;
        sy += a.y;
    }
    int cnt = end - beg;
    float inv = 1.f / (float)(cnt > 0 ? cnt : 1);
    ((float2*)g_emean)[w * 32 + lane] = make_float2(sx * inv, sy * inv);
}

// ---------------- kernel: per-node output (warp per node) ----------------
__global__ void node_out_kernel(const float* __restrict__ bout, float* __restrict__ out) {
    int w = (blockIdx.x * 256 + threadIdx.x) >> 5;
    int lane = threadIdx.x & 31;
    if (w >= NN) return;
    int beg = g_nptr[w], end = g_nptr[w + 1];
    const float2* E2 = (const float2*)g_emean;
    float sx = 0.f, sy = 0.f;
    int j = beg;
    for (; j + 4 <= end; j += 4) {
        int s0 = g_nmem[j], s1 = g_nmem[j + 1], s2 = g_nmem[j + 2], s3 = g_nmem[j + 3];
        float2 a = E2[s0 * 32 + lane];
        float2 b = E2[s1 * 32 + lane];
        float2 c = E2[s2 * 32 + lane];
        float2 d = E2[s3 * 32 + lane];
        sx += (a.x + b.x) + (c.x + d.x);
        sy += (a.y + b.y) + (c.y + d.y);
    }
    for (; j < end; j++) {
        int s0 = g_nmem[j];
        float2 a = E2[s0 * 32 + lane];
        sx += a.x;
        sy += a.y;
    }
    float2 bo = ((const float2*)bout)[lane];
    ((float2*)out)[w * 32 + lane] = make_float2(bo.x + 0.5f * sx, bo.y + 0.5f * sy);
}

// ---------------- launcher ----------------
extern "C" void kernel_launch(void* const* d_in, const int* in_sizes, int n_in,
                              void* d_out, int out_size) {
    const float* x = (const float*)d_in[0];
    const int* hi1 = (const int*)d_in[1];
    const int* hi2 = (const int*)d_in[2];
    const float* W1 = (const float*)d_in[3];
    const float* b1 = (const float*)d_in[4];
    const float* W2 = (const float*)d_in[5];
    const float* b2 = (const float*)d_in[6];
    const float* Wout = (const float*)d_in[7];
    const float* bout = (const float*)d_in[8];
    float* out = (float*)d_out;

    int nnz1 = in_sizes[1] / 2;
    int nnz2 = in_sizes[2] / 2;
    int tot = nnz1 + nnz2;

    // 1) zero histograms
    zero_kernel<<<(2 * NE + NN + 255) / 256, 256>>>();
    // 2) fold weights (independent of CSR build)
    fold_kernel<<<65, 256>>>(W1, b1, W2, b2, Wout);
    // 3) histogram
    hist_kernel<<<(tot + 255) / 256, 256>>>(hi1, hi2, nnz1, nnz2);
    // 4) scan -> CSR pointers
    scan_kernel<<<2, 1024>>>();
    // 5) fill CSR member lists
    fill_kernel<<<(tot + 255) / 256, 256>>>(hi1, hi2, nnz1, nnz2);
    // 6) Y = x @ Vcat^T + ccat
    gemm_kernel<<<(NN + 63) / 64, 128>>>(x);
    // 7) per-edge-slot mean
    edge_mean_kernel<<<(2 * NE * 32 + 255) / 256, 256>>>();
    // 8) per-node gather + bias -> out
    node_out_kernel<<<(NN * 32 + 255) / 256, 256>>>(bout, out);
}

// round 2
// speedup vs baseline: 1.0220x; 1.0220x over previous
#include <cuda_runtime.h>
#include <cuda_fp16.h>

// Problem constants (fixed by the reference generator)
#define NN 10000     // nodes
#define NE 4000      // edges

#define MAXM (4 * 1024 * 1024)  // max total incidence entries across both scales

// ---------------- device scratch (no allocations allowed) ----------------
__device__ float g_VT[128 * 128];        // folded weights, transposed: VT[k*128 + j]
__device__ float g_cc[128];              // folded biases
__device__ __half g_Y[NN * 128];         // Y = x @ Vcat^T + ccat  (fp16 staging)
__device__ __half g_emean[2 * NE * 64];  // per-(scale,edge) mean  (fp16 staging)
__device__ int g_ecnt[2 * NE + 1], g_eptr[2 * NE + 1], g_epos[2 * NE];
__device__ int g_ncnt[NN + 1], g_nptr[NN + 1], g_npos[NN];
__device__ int g_emem[MAXM];             // CSR by edge-slot: member node ids
__device__ int g_nmem[MAXM];             // CSR by node: member edge-slot ids

// ---------------- K1: zero histograms + fold Wout into W1/W2,b1/b2 ----------------
// blocks 0..63: VT fold; block 64: bias fold; blocks 65..: zeroing
__global__ void init_kernel(const float* __restrict__ W1, const float* __restrict__ b1,
                            const float* __restrict__ W2, const float* __restrict__ b2,
                            const float* __restrict__ Wout) {
    int bb = blockIdx.x;
    if (bb < 64) {
        int idx = bb * 256 + threadIdx.x;  // [0, 16384)
        int j = idx >> 7, k = idx & 127;
        int s = j >> 6, jo = j & 63;
        const float* W = s ? W2 : W1;
        float sum = 0.f;
#pragma unroll 8
        for (int h = 0; h < 128; h++) sum = fmaf(Wout[jo * 128 + h], W[h * 128 + k], sum);
        g_VT[k * 128 + j] = sum;
    } else if (bb == 64) {
        int j = threadIdx.x;
        if (j < 128) {
            int s = j >> 6, jo = j & 63;
            const float* b = s ? b2 : b1;
            float sum = 0.f;
#pragma unroll 8
            for (int h = 0; h < 128; h++) sum = fmaf(Wout[jo * 128 + h], b[h], sum);
            g_cc[j] = sum;
        }
    } else {
        int i = (bb - 65) * 256 + threadIdx.x;
        if (i < 2 * NE) g_ecnt[i] = 0;
        if (i < NN) g_ncnt[i] = 0;
    }
}

// ---------------- K2: histogram of edge slots and nodes ----------------
__global__ void hist_kernel(const int* __restrict__ hi1, const int* __restrict__ hi2,
                            int nnz1, int nnz2) {
    int k = blockIdx.x * blockDim.x + threadIdx.x;
    int tot = nnz1 + nnz2;
    if (k >= tot) return;
    int node, slot;
    if (k < nnz1) { node = __ldg(&hi1[k]); slot = __ldg(&hi1[nnz1 + k]); }
    else { int kk = k - nnz1; node = __ldg(&hi2[kk]); slot = NE + __ldg(&hi2[nnz2 + kk]); }
    atomicAdd(&g_ecnt[slot], 1);
    atomicAdd(&g_ncnt[node], 1);
}

// ---------------- K3: exclusive scan via warp shuffles ----------------
__device__ __forceinline__ void block_scan(const int* cnt, int* ptr, int* pos, int n) {
    __shared__ int wsum[32];
    __shared__ int s_tot;
    int t = threadIdx.x, lane = t & 31, wid = t >> 5;
    int carry = 0;
    for (int base = 0; base < n; base += 1024) {
        int i = base + t;
        int v = (i < n) ? cnt[i] : 0;
        int inc = v;
#pragma unroll
        for (int o = 1; o < 32; o <<= 1) {
            int u = __shfl_up_sync(~0u, inc, o);
            if (lane >= o) inc += u;
        }
        if (lane == 31) wsum[wid] = inc;
        __syncthreads();
        if (wid == 0) {
            int w = wsum[lane];
            int wi = w;
#pragma unroll
            for (int o = 1; o < 32; o <<= 1) {
                int u = __shfl_up_sync(~0u, wi, o);
                if (lane >= o) wi += u;
            }
            wsum[lane] = wi - w;  // exclusive warp offsets
            if (lane == 31) s_tot = wi;
        }
        __syncthreads();
        int excl = carry + wsum[wid] + (inc - v);
        if (i < n) { ptr[i] = excl; pos[i] = excl; }
        carry += s_tot;
        __syncthreads();  // protect wsum/s_tot before next tile
    }
    if (t == 0) ptr[n] = carry;
}

__global__ void scan_kernel() {
    if (blockIdx.x == 0) block_scan(g_ecnt, g_eptr, g_epos, 2 * NE);
    else block_scan(g_ncnt, g_nptr, g_npos, NN);
}

// ---------------- K4: fill CSR member arrays + GEMM (fused, disjoint pipes) ----------------
#define GEMM_BLOCKS ((NN + 63) / 64)  // 157

#define FMA4(a, sc, v)                 \
    a.x = fmaf(sc, v.x, a.x);          \
    a.y = fmaf(sc, v.y, a.y);          \
    a.z = fmaf(sc, v.z, a.z);          \
    a.w = fmaf(sc, v.w, a.w);

__global__ __launch_bounds__(128) void fillgemm_kernel(const float* __restrict__ x,
                                                       const int* __restrict__ hi1,
                                                       const int* __restrict__ hi2,
                                                       int nnz1, int nnz2) {
    if (blockIdx.x < GEMM_BLOCKS) {
        // ---- GEMM: Y[row][j] = sum_k x[row][k] * VT[k][j] + cc[j], fp16 out ----
        int tx = threadIdx.x & 31;   // cols tx*4 .. tx*4+3
        int ty = threadIdx.x >> 5;   // 16-row group
        int row0 = blockIdx.x * 64 + ty * 16;
        const float4* x4 = (const float4*)x;
        const float4* v4 = (const float4*)g_VT;

        int rbase[16];
#pragma unroll
        for (int r = 0; r < 16; r++) {
            int row = row0 + r;
            rbase[r] = (row < NN ? row : NN - 1) * 32;
        }
        float4 acc[16];
#pragma unroll
        for (int r = 0; r < 16; r++) acc[r] = make_float4(0.f, 0.f, 0.f, 0.f);

#pragma unroll 2
        for (int k4 = 0; k4 < 32; k4++) {
            float4 v0 = v4[(4 * k4 + 0) * 32 + tx];
            float4 v1 = v4[(4 * k4 + 1) * 32 + tx];
            float4 v2 = v4[(4 * k4 + 2) * 32 + tx];
            float4 v3 = v4[(4 * k4 + 3) * 32 + tx];
#pragma unroll
            for (int r = 0; r < 16; r++) {
                float4 xq = x4[rbase[r] + k4];
                FMA4(acc[r], xq.x, v0);
                FMA4(acc[r], xq.y, v1);
                FMA4(acc[r], xq.z, v2);
                FMA4(acc[r], xq.w, v3);
            }
        }
        float4 c = ((const float4*)g_cc)[tx];
#pragma unroll
        for (int r = 0; r < 16; r++) {
            int row = row0 + r;
            if (row < NN) {
                union { __half2 h[2]; uint2 u; } cv;
                cv.h[0] = __floats2half2_rn(acc[r].x + c.x, acc[r].y + c.y);
                cv.h[1] = __floats2half2_rn(acc[r].z + c.z, acc[r].w + c.w);
                ((uint2*)g_Y)[row * 32 + tx] = cv.u;
            }
        }
    } else {
        // ---- fill CSR member lists ----
        int k = (blockIdx.x - GEMM_BLOCKS) * 128 + threadIdx.x;
        int tot = nnz1 + nnz2;
        if (k >= tot) return;
        int node, slot;
        if (k < nnz1) { node = __ldg(&hi1[k]); slot = __ldg(&hi1[nnz1 + k]); }
        else { int kk = k - nnz1; node = __ldg(&hi2[kk]); slot = NE + __ldg(&hi2[nnz2 + kk]); }
        int p = atomicAdd(&g_epos[slot], 1);
        g_emem[p] = node;
        int q = atomicAdd(&g_npos[node], 1);
        g_nmem[q] = slot;
    }
}

// ---------------- K5: per-edge-slot mean (warp per slot, fp16 in/out) ----------------
__global__ void edge_mean_kernel() {
    int w = (blockIdx.x * 256 + threadIdx.x) >> 5;
    int lane = threadIdx.x & 31;
    if (w >= 2 * NE) return;
    int beg = g_eptr[w], end = g_eptr[w + 1];
    int col = ((w >= NE) ? 32 : 0) + lane;  // half2 column within 64-half2 Y row
    const __half2* Y2 = (const __half2*)g_Y;
    float sx = 0.f, sy = 0.f;
    int j = beg;
    for (; j + 8 <= end; j += 8) {
        float2 f[8];
#pragma unroll
        for (int u = 0; u < 8; u++) {
            int n0 = g_emem[j + u];
            f[u] = __half22float2(Y2[n0 * 64 + col]);
        }
#pragma unroll
        for (int u = 0; u < 8; u++) { sx += f[u].x; sy += f[u].y; }
    }
    for (; j < end; j++) {
        int n0 = g_emem[j];
        float2 a = __half22float2(Y2[n0 * 64 + col]);
        sx += a.x;
        sy += a.y;
    }
    int cnt = end - beg;
    float inv = 1.f / (float)(cnt > 0 ? cnt : 1);
    ((__half2*)g_emean)[w * 32 + lane] = __floats2half2_rn(sx * inv, sy * inv);
}

// ---------------- K6: per-node output (warp per node) ----------------
__global__ void node_out_kernel(const float* __restrict__ bout, float* __restrict__ out) {
    int w = (blockIdx.x * 256 + threadIdx.x) >> 5;
    int lane = threadIdx.x & 31;
    if (w >= NN) return;
    int beg = g_nptr[w], end = g_nptr[w + 1];
    const __half2* E2 = (const __half2*)g_emean;
    float sx = 0.f, sy = 0.f;
    int j = beg;
    for (; j + 8 <= end; j += 8) {
        float2 f[8];
#pragma unroll
        for (int u = 0; u < 8; u++) {
            int s0 = g_nmem[j + u];
            f[u] = __half22float2(E2[s0 * 32 + lane]);
        }
#pragma unroll
        for (int u = 0; u < 8; u++) { sx += f[u].x; sy += f[u].y; }
    }
    for (; j < end; j++) {
        int s0 = g_nmem[j];
        float2 a = __half22float2(E2[s0 * 32 + lane]);
        sx += a.x;
        sy += a.y;
    }
    float2 bo = ((const float2*)bout)[lane];
    ((float2*)out)[w * 32 + lane] = make_float2(bo.x + 0.5f * sx, bo.y + 0.5f * sy);
}

// ---------------- launcher ----------------
extern "C" void kernel_launch(void* const* d_in, const int* in_sizes, int n_in,
                              void* d_out, int out_size) {
    const float* x = (const float*)d_in[0];
    const int* hi1 = (const int*)d_in[1];
    const int* hi2 = (const int*)d_in[2];
    const float* W1 = (const float*)d_in[3];
    const float* b1 = (const float*)d_in[4];
    const float* W2 = (const float*)d_in[5];
    const float* b2 = (const float*)d_in[6];
    const float* Wout = (const float*)d_in[7];
    const float* bout = (const float*)d_in[8];
    float* out = (float*)d_out;

    int nnz1 = in_sizes[1] / 2;
    int nnz2 = in_sizes[2] / 2;
    int tot = nnz1 + nnz2;

    // K1: zero + fold (65 fold blocks + zero blocks)
    init_kernel<<<65 + (2 * NE + NN + 255) / 256, 256>>>(W1, b1, W2, b2, Wout);
    // K2: histogram
    hist_kernel<<<(tot + 255) / 256, 256>>>(hi1, hi2, nnz1, nnz2);
    // K3: scan -> CSR pointers (fast warp-shuffle scan)
    scan_kernel<<<2, 1024>>>();
    // K4: fill CSR + GEMM fused (disjoint pipes overlap)
    fillgemm_kernel<<<GEMM_BLOCKS + (tot + 127) / 128, 128>>>(x, hi1, hi2, nnz1, nnz2);
    // K5: per-edge-slot mean
    edge_mean_kernel<<<(2 * NE * 32 + 255) / 256, 256>>>();
    // K6: per-node gather + bias -> out
    node_out_kernel<<<(NN * 32 + 255) / 256, 256>>>(bout, out);
}

// round 3
// speedup vs baseline: 1.2990x; 1.2710x over previous
#include <cuda_runtime.h>
#include <cuda_fp16.h>

#define NN 10000
#define NE 4000
#define MAXM (4 * 1024 * 1024)

// ---------------- device scratch ----------------
__device__ float g_VT[128 * 128];        // folded weights, transposed: VT[k*128 + j]
__device__ float g_cc[128];              // folded biases
__device__ __half g_Y[NN * 128];         // fp16 staging
__device__ __half g_emean[2 * NE * 64];  // fp16 staging
__device__ int g_ecnt[2 * NE + 1], g_eptr[2 * NE + 1], g_epos[2 * NE];
__device__ int g_ncnt[NN + 1], g_nptr[NN + 1], g_npos[NN];
__device__ int g_emem[MAXM];
__device__ int g_nmem[MAXM];

// ---------------- K1: zero histograms + fold weights ----------------
__global__ void init_kernel(const float* __restrict__ W1, const float* __restrict__ b1,
                            const float* __restrict__ W2, const float* __restrict__ b2,
                            const float* __restrict__ Wout) {
    int bb = blockIdx.x;
    if (bb < 64) {
        int idx = bb * 256 + threadIdx.x;
        int j = idx >> 7, k = idx & 127;
        int s = j >> 6, jo = j & 63;
        const float* W = s ? W2 : W1;
        float sum = 0.f;
#pragma unroll 8
        for (int h = 0; h < 128; h++) sum = fmaf(Wout[jo * 128 + h], W[h * 128 + k], sum);
        g_VT[k * 128 + j] = sum;
    } else if (bb == 64) {
        int j = threadIdx.x;
        if (j < 128) {
            int s = j >> 6, jo = j & 63;
            const float* b = s ? b2 : b1;
            float sum = 0.f;
#pragma unroll 8
            for (int h = 0; h < 128; h++) sum = fmaf(Wout[jo * 128 + h], b[h], sum);
            g_cc[j] = sum;
        }
    } else {
        int i = (bb - 65) * 256 + threadIdx.x;
        if (i < 2 * NE) g_ecnt[i] = 0;
        if (i < NN) g_ncnt[i] = 0;
    }
}

// ---------------- K2: GEMM (32 rows x 128 cols / block) + histogram, fused ----------------
#define GEMM_BLOCKS ((NN + 31) / 32)  // 313

#define FMA4(a, sc, v)                 \
    a.x = fmaf(sc, v.x, a.x);          \
    a.y = fmaf(sc, v.y, a.y);          \
    a.z = fmaf(sc, v.z, a.z);          \
    a.w = fmaf(sc, v.w, a.w);

__global__ __launch_bounds__(256) void gemmhist_kernel(const float* __restrict__ x,
                                                       const int* __restrict__ hi1,
                                                       const int* __restrict__ hi2,
                                                       int nnz1, int nnz2) {
    if (blockIdx.x < GEMM_BLOCKS) {
        // thread: 4 rows x 4 cols.  tx -> col group, ty -> row group.
        int tx = threadIdx.x & 31;
        int ty = threadIdx.x >> 5;       // 0..7
        int row0 = blockIdx.x * 32 + ty * 4;
        const float4* x4 = (const float4*)x;
        const float4* v4 = (const float4*)g_VT;

        int rb0 = (row0 + 0 < NN ? row0 + 0 : NN - 1) * 32;
        int rb1 = (row0 + 1 < NN ? row0 + 1 : NN - 1) * 32;
        int rb2 = (row0 + 2 < NN ? row0 + 2 : NN - 1) * 32;
        int rb3 = (row0 + 3 < NN ? row0 + 3 : NN - 1) * 32;

        float4 a0 = make_float4(0.f, 0.f, 0.f, 0.f), a1 = a0, a2 = a0, a3 = a0;

#pragma unroll 4
        for (int k4 = 0; k4 < 32; k4++) {
            float4 v0 = v4[(4 * k4 + 0) * 32 + tx];
            float4 v1 = v4[(4 * k4 + 1) * 32 + tx];
            float4 v2 = v4[(4 * k4 + 2) * 32 + tx];
            float4 v3 = v4[(4 * k4 + 3) * 32 + tx];
            float4 q;
            q = x4[rb0 + k4];
            FMA4(a0, q.x, v0); FMA4(a0, q.y, v1); FMA4(a0, q.z, v2); FMA4(a0, q.w, v3);
            q = x4[rb1 + k4];
            FMA4(a1, q.x, v0); FMA4(a1, q.y, v1); FMA4(a1, q.z, v2); FMA4(a1, q.w, v3);
            q = x4[rb2 + k4];
            FMA4(a2, q.x, v0); FMA4(a2, q.y, v1); FMA4(a2, q.z, v2); FMA4(a2, q.w, v3);
            q = x4[rb3 + k4];
            FMA4(a3, q.x, v0); FMA4(a3, q.y, v1); FMA4(a3, q.z, v2); FMA4(a3, q.w, v3);
        }
        float4 c = ((const float4*)g_cc)[tx];
        a0.x += c.x; a0.y += c.y; a0.z += c.z; a0.w += c.w;
        a1.x += c.x; a1.y += c.y; a1.z += c.z; a1.w += c.w;
        a2.x += c.x; a2.y += c.y; a2.z += c.z; a2.w += c.w;
        a3.x += c.x; a3.y += c.y; a3.z += c.z; a3.w += c.w;

        union { __half2 h[2]; uint2 u; } cv;
#define STORE_ROW(rr, aa)                                             \
        if (row0 + rr < NN) {                                         \
            cv.h[0] = __floats2half2_rn(aa.x, aa.y);                  \
            cv.h[1] = __floats2half2_rn(aa.z, aa.w);                  \
            ((uint2*)g_Y)[(row0 + rr) * 32 + tx] = cv.u;              \
        }
        STORE_ROW(0, a0) STORE_ROW(1, a1) STORE_ROW(2, a2) STORE_ROW(3, a3)
#undef STORE_ROW
    } else {
        int k = (blockIdx.x - GEMM_BLOCKS) * 256 + threadIdx.x;
        int tot = nnz1 + nnz2;
        if (k >= tot) return;
        int node, slot;
        if (k < nnz1) { node = __ldg(&hi1[k]); slot = __ldg(&hi1[nnz1 + k]); }
        else { int kk = k - nnz1; node = __ldg(&hi2[kk]); slot = NE + __ldg(&hi2[nnz2 + kk]); }
        atomicAdd(&g_ecnt[slot], 1);
        atomicAdd(&g_ncnt[node], 1);
    }
}

// ---------------- K3: exclusive scan via warp shuffles ----------------
__device__ __forceinline__ void block_scan(const int* cnt, int* ptr, int* pos, int n) {
    __shared__ int wsum[32];
    __shared__ int s_tot;
    int t = threadIdx.x, lane = t & 31, wid = t >> 5;
    int carry = 0;
    for (int base = 0; base < n; base += 1024) {
        int i = base + t;
        int v = (i < n) ? cnt[i] : 0;
        int inc = v;
#pragma unroll
        for (int o = 1; o < 32; o <<= 1) {
            int u = __shfl_up_sync(~0u, inc, o);
            if (lane >= o) inc += u;
        }
        if (lane == 31) wsum[wid] = inc;
        __syncthreads();
        if (wid == 0) {
            int w = wsum[lane];
            int wi = w;
#pragma unroll
            for (int o = 1; o < 32; o <<= 1) {
                int u = __shfl_up_sync(~0u, wi, o);
                if (lane >= o) wi += u;
            }
            wsum[lane] = wi - w;
            if (lane == 31) s_tot = wi;
        }
        __syncthreads();
        int excl = carry + wsum[wid] + (inc - v);
        if (i < n) { ptr[i] = excl; pos[i] = excl; }
        carry += s_tot;
        __syncthreads();
    }
    if (t == 0) ptr[n] = carry;
}

__global__ void scan_kernel() {
    if (blockIdx.x == 0) block_scan(g_ecnt, g_eptr, g_epos, 2 * NE);
    else block_scan(g_ncnt, g_nptr, g_npos, NN);
}

// ---------------- K4: fill CSR member arrays (standalone, lean) ----------------
__global__ __launch_bounds__(256) void fill_kernel(const int* __restrict__ hi1,
                                                   const int* __restrict__ hi2,
                                                   int nnz1, int nnz2) {
    int k = blockIdx.x * 256 + threadIdx.x;
    int tot = nnz1 + nnz2;
    if (k >= tot) return;
    int node, slot;
    if (k < nnz1) { node = __ldg(&hi1[k]); slot = __ldg(&hi1[nnz1 + k]); }
    else { int kk = k - nnz1; node = __ldg(&hi2[kk]); slot = NE + __ldg(&hi2[nnz2 + kk]); }
    int p = atomicAdd(&g_epos[slot], 1);
    g_emem[p] = node;
    int q = atomicAdd(&g_npos[node], 1);
    g_nmem[q] = slot;
}

// ---------------- K5: per-edge-slot mean (warp per slot) ----------------
__global__ void edge_mean_kernel() {
    int w = (blockIdx.x * 256 + threadIdx.x) >> 5;
    int lane = threadIdx.x & 31;
    if (w >= 2 * NE) return;
    int beg = g_eptr[w], end = g_eptr[w + 1];
    int col = ((w >= NE) ? 32 : 0) + lane;
    const __half2* Y2 = (const __half2*)g_Y;
    float sx = 0.f, sy = 0.f;
    int j = beg;
    for (; j + 8 <= end; j += 8) {
        float2 f[8];
#pragma unroll
        for (int u = 0; u < 8; u++) {
            int n0 = g_emem[j + u];
            f[u] = __half22float2(Y2[n0 * 64 + col]);
        }
#pragma unroll
        for (int u = 0; u < 8; u++) { sx += f[u].x; sy += f[u].y; }
    }
    for (; j < end; j++) {
        int n0 = g_emem[j];
        float2 a = __half22float2(Y2[n0 * 64 + col]);
        sx += a.x;
        sy += a.y;
    }
    int cnt = end - beg;
    float inv = 1.f / (float)(cnt > 0 ? cnt : 1);
    ((__half2*)g_emean)[w * 32 + lane] = __floats2half2_rn(sx * inv, sy * inv);
}

// ---------------- K6: per-node output (warp per node) ----------------
__global__ void node_out_kernel(const float* __restrict__ bout, float* __restrict__ out) {
    int w = (blockIdx.x * 256 + threadIdx.x) >> 5;
    int lane = threadIdx.x & 31;
    if (w >= NN) return;
    int beg = g_nptr[w], end = g_nptr[w + 1];
    const __half2* E2 = (const __half2*)g_emean;
    float sx = 0.f, sy = 0.f;
    int j = beg;
    for (; j + 8 <= end; j += 8) {
        float2 f[8];
#pragma unroll
        for (int u = 0; u < 8; u++) {
            int s0 = g_nmem[j + u];
            f[u] = __half22float2(E2[s0 * 32 + lane]);
        }
#pragma unroll
        for (int u = 0; u < 8; u++) { sx += f[u].x; sy += f[u].y; }
    }
    for (; j < end; j++) {
        int s0 = g_nmem[j];
        float2 a = __half22float2(E2[s0 * 32 + lane]);
        sx += a.x;
        sy += a.y;
    }
    float2 bo = ((const float2*)bout)[lane];
    ((float2*)out)[w * 32 + lane] = make_float2(bo.x + 0.5f * sx, bo.y + 0.5f * sy);
}

// ---------------- launcher ----------------
extern "C" void kernel_launch(void* const* d_in, const int* in_sizes, int n_in,
                              void* d_out, int out_size) {
    const float* x = (const float*)d_in[0];
    const int* hi1 = (const int*)d_in[1];
    const int* hi2 = (const int*)d_in[2];
    const float* W1 = (const float*)d_in[3];
    const float* b1 = (const float*)d_in[4];
    const float* W2 = (const float*)d_in[5];
    const float* b2 = (const float*)d_in[6];
    const float* Wout = (const float*)d_in[7];
    const float* bout = (const float*)d_in[8];
    float* out = (float*)d_out;

    int nnz1 = in_sizes[1] / 2;
    int nnz2 = in_sizes[2] / 2;
    int tot = nnz1 + nnz2;

    init_kernel<<<65 + (2 * NE + NN + 255) / 256, 256>>>(W1, b1, W2, b2, Wout);
    gemmhist_kernel<<<GEMM_BLOCKS + (tot + 255) / 256, 256>>>(x, hi1, hi2, nnz1, nnz2);
    scan_kernel<<<2, 1024>>>();
    fill_kernel<<<(tot + 255) / 256, 256>>>(hi1, hi2, nnz1, nnz2);
    edge_mean_kernel<<<(2 * NE * 32 + 255) / 256, 256>>>();
    node_out_kernel<<<(NN * 32 + 255) / 256, 256>>>(bout, out);
}

// round 4
// speedup vs baseline: 1.3755x; 1.0589x over previous
#include <cuda_runtime.h>
#include <cuda_fp16.h>

#define NN 10000
#define NE 4000
#define MAXM (4 * 1024 * 1024)

// ---------------- device scratch ----------------
__device__ float g_VT[128 * 128];        // folded weights, transposed
__device__ float g_cc[128];              // folded biases
__device__ __half g_Y[NN * 128];         // fp16 staging
__device__ __half g_emean[2 * NE * 64];  // fp16 staging
__device__ int g_ecnt[2 * NE + 1], g_eptr[2 * NE + 1], g_epos[2 * NE];
__device__ int g_n1cnt[NN + 1], g_n1ptr[NN + 1], g_n1pos[NN];
__device__ int g_n2cnt[NN + 1], g_n2ptr[NN + 1];
__device__ int g_emem[MAXM];     // CSR by edge-slot: member node ids (both scales)
__device__ int g_nmem1[MAXM];    // CSR by node: scale-1 edge ids only (small)

// ---------------- K1: zero histograms + fold weights ----------------
__global__ void init_kernel(const float* __restrict__ W1, const float* __restrict__ b1,
                            const float* __restrict__ W2, const float* __restrict__ b2,
                            const float* __restrict__ Wout) {
    int bb = blockIdx.x;
    if (bb < 64) {
        int idx = bb * 256 + threadIdx.x;
        int j = idx >> 7, k = idx & 127;
        int s = j >> 6, jo = j & 63;
        const float* W = s ? W2 : W1;
        float sum = 0.f;
#pragma unroll 8
        for (int h = 0; h < 128; h++) sum = fmaf(Wout[jo * 128 + h], W[h * 128 + k], sum);
        g_VT[k * 128 + j] = sum;
    } else if (bb == 64) {
        int j = threadIdx.x;
        if (j < 128) {
            int s = j >> 6, jo = j & 63;
            const float* b = s ? b2 : b1;
            float sum = 0.f;
#pragma unroll 8
            for (int h = 0; h < 128; h++) sum = fmaf(Wout[jo * 128 + h], b[h], sum);
            g_cc[j] = sum;
        }
    } else {
        int i = (bb - 65) * 256 + threadIdx.x;
        if (i < 2 * NE) g_ecnt[i] = 0;
        if (i < NN) { g_n1cnt[i] = 0; g_n2cnt[i] = 0; }
    }
}

// ---------------- K2: GEMM (32x128/block) + histogram, fused ----------------
#define GEMM_BLOCKS ((NN + 31) / 32)  // 313

#define FMA4(a, sc, v)                 \
    a.x = fmaf(sc, v.x, a.x);          \
    a.y = fmaf(sc, v.y, a.y);          \
    a.z = fmaf(sc, v.z, a.z);          \
    a.w = fmaf(sc, v.w, a.w);

__global__ __launch_bounds__(256) void gemmhist_kernel(const float* __restrict__ x,
                                                       const int* __restrict__ hi1,
                                                       const int* __restrict__ hi2,
                                                       int nnz1, int nnz2) {
    if (blockIdx.x < GEMM_BLOCKS) {
        int tx = threadIdx.x & 31;
        int ty = threadIdx.x >> 5;
        int row0 = blockIdx.x * 32 + ty * 4;
        const float4* x4 = (const float4*)x;
        const float4* v4 = (const float4*)g_VT;

        int rb0 = (row0 + 0 < NN ? row0 + 0 : NN - 1) * 32;
        int rb1 = (row0 + 1 < NN ? row0 + 1 : NN - 1) * 32;
        int rb2 = (row0 + 2 < NN ? row0 + 2 : NN - 1) * 32;
        int rb3 = (row0 + 3 < NN ? row0 + 3 : NN - 1) * 32;

        float4 a0 = make_float4(0.f, 0.f, 0.f, 0.f), a1 = a0, a2 = a0, a3 = a0;

#pragma unroll 4
        for (int k4 = 0; k4 < 32; k4++) {
            float4 v0 = v4[(4 * k4 + 0) * 32 + tx];
            float4 v1 = v4[(4 * k4 + 1) * 32 + tx];
            float4 v2 = v4[(4 * k4 + 2) * 32 + tx];
            float4 v3 = v4[(4 * k4 + 3) * 32 + tx];
            float4 q;
            q = x4[rb0 + k4];
            FMA4(a0, q.x, v0); FMA4(a0, q.y, v1); FMA4(a0, q.z, v2); FMA4(a0, q.w, v3);
            q = x4[rb1 + k4];
            FMA4(a1, q.x, v0); FMA4(a1, q.y, v1); FMA4(a1, q.z, v2); FMA4(a1, q.w, v3);
            q = x4[rb2 + k4];
            FMA4(a2, q.x, v0); FMA4(a2, q.y, v1); FMA4(a2, q.z, v2); FMA4(a2, q.w, v3);
            q = x4[rb3 + k4];
            FMA4(a3, q.x, v0); FMA4(a3, q.y, v1); FMA4(a3, q.z, v2); FMA4(a3, q.w, v3);
        }
        float4 c = ((const float4*)g_cc)[tx];
        a0.x += c.x; a0.y += c.y; a0.z += c.z; a0.w += c.w;
        a1.x += c.x; a1.y += c.y; a1.z += c.z; a1.w += c.w;
        a2.x += c.x; a2.y += c.y; a2.z += c.z; a2.w += c.w;
        a3.x += c.x; a3.y += c.y; a3.z += c.z; a3.w += c.w;

        union { __half2 h[2]; uint2 u; } cv;
#define STORE_ROW(rr, aa)                                             \
        if (row0 + rr < NN) {                                         \
            cv.h[0] = __floats2half2_rn(aa.x, aa.y);                  \
            cv.h[1] = __floats2half2_rn(aa.z, aa.w);                  \
            ((uint2*)g_Y)[(row0 + rr) * 32 + tx] = cv.u;              \
        }
        STORE_ROW(0, a0) STORE_ROW(1, a1) STORE_ROW(2, a2) STORE_ROW(3, a3)
#undef STORE_ROW
    } else {
        int k = (blockIdx.x - GEMM_BLOCKS) * 256 + threadIdx.x;
        int tot = nnz1 + nnz2;
        if (k >= tot) return;
        if (k < nnz1) {
            int node = __ldg(&hi1[k]), edge = __ldg(&hi1[nnz1 + k]);
            atomicAdd(&g_ecnt[edge], 1);
            atomicAdd(&g_n1cnt[node], 1);
        } else {
            int kk = k - nnz1;
            int node = __ldg(&hi2[kk]), edge = __ldg(&hi2[nnz2 + kk]);
            atomicAdd(&g_ecnt[NE + edge], 1);
            atomicAdd(&g_n2cnt[node], 1);
        }
    }
}

// ---------------- K3: exclusive scans (warp-shuffle) ----------------
__device__ __forceinline__ void block_scan(const int* cnt, int* ptr, int* pos, int n) {
    __shared__ int wsum[32];
    __shared__ int s_tot;
    int t = threadIdx.x, lane = t & 31, wid = t >> 5;
    int carry = 0;
    for (int base = 0; base < n; base += 1024) {
        int i = base + t;
        int v = (i < n) ? cnt[i] : 0;
        int inc = v;
#pragma unroll
        for (int o = 1; o < 32; o <<= 1) {
            int u = __shfl_up_sync(~0u, inc, o);
            if (lane >= o) inc += u;
        }
        if (lane == 31) wsum[wid] = inc;
        __syncthreads();
        if (wid == 0) {
            int w = wsum[lane];
            int wi = w;
#pragma unroll
            for (int o = 1; o < 32; o <<= 1) {
                int u = __shfl_up_sync(~0u, wi, o);
                if (lane >= o) wi += u;
            }
            wsum[lane] = wi - w;
            if (lane == 31) s_tot = wi;
        }
        __syncthreads();
        int excl = carry + wsum[wid] + (inc - v);
        if (i < n) { ptr[i] = excl; if (pos) pos[i] = excl; }
        carry += s_tot;
        __syncthreads();
    }
    if (t == 0) ptr[n] = carry;
}

__global__ void scan_kernel() {
    if (blockIdx.x == 0) block_scan(g_ecnt, g_eptr, g_epos, 2 * NE);
    else if (blockIdx.x == 1) block_scan(g_n1cnt, g_n1ptr, g_n1pos, NN);
    else block_scan(g_n2cnt, g_n2ptr, (int*)0, NN);
}

// ---------------- K4: fill edge-CSR (batched atomics) + scale1 node-CSR ----------------
// blocks [0, B2): scale-2 entries, 4 per thread.  blocks [B2, ...): scale-1 entries.
__global__ __launch_bounds__(256) void fill_kernel(const int* __restrict__ hi1,
                                                   const int* __restrict__ hi2,
                                                   int nnz1, int nnz2, int B2) {
    if (blockIdx.x < B2) {
        int i = (blockIdx.x * 256 + threadIdx.x) * 4;
        if (i >= nnz2) return;
        if (i + 4 <= nnz2) {
            int n0 = __ldg(&hi2[i]),     n1 = __ldg(&hi2[i + 1]);
            int n2 = __ldg(&hi2[i + 2]), n3 = __ldg(&hi2[i + 3]);
            int e0 = __ldg(&hi2[nnz2 + i]),     e1 = __ldg(&hi2[nnz2 + i + 1]);
            int e2 = __ldg(&hi2[nnz2 + i + 2]), e3 = __ldg(&hi2[nnz2 + i + 3]);
            int p0 = atomicAdd(&g_epos[NE + e0], 1);
            int p1 = atomicAdd(&g_epos[NE + e1], 1);
            int p2 = atomicAdd(&g_epos[NE + e2], 1);
            int p3 = atomicAdd(&g_epos[NE + e3], 1);
            g_emem[p0] = n0; g_emem[p1] = n1; g_emem[p2] = n2; g_emem[p3] = n3;
        } else {
            for (int u = i; u < nnz2; u++) {
                int n0 = __ldg(&hi2[u]), e0 = __ldg(&hi2[nnz2 + u]);
                int p = atomicAdd(&g_epos[NE + e0], 1);
                g_emem[p] = n0;
            }
        }
    } else {
        int k = (blockIdx.x - B2) * 256 + threadIdx.x;
        if (k >= nnz1) return;
        int node = __ldg(&hi1[k]), edge = __ldg(&hi1[nnz1 + k]);
        int p = atomicAdd(&g_epos[edge], 1);
        g_emem[p] = node;
        int q = atomicAdd(&g_n1pos[node], 1);
        g_nmem1[q] = edge;
    }
}

// ---------------- K5: per-edge-slot mean (warp per slot) ----------------
__global__ void edge_mean_kernel() {
    int w = (blockIdx.x * 256 + threadIdx.x) >> 5;
    int lane = threadIdx.x & 31;
    if (w >= 2 * NE) return;
    int beg = g_eptr[w], end = g_eptr[w + 1];
    int col = ((w >= NE) ? 32 : 0) + lane;
    const __half2* Y2 = (const __half2*)g_Y;
    float sx = 0.f, sy = 0.f;
    int j = beg;
    for (; j + 8 <= end; j += 8) {
        float2 f[8];
#pragma unroll
        for (int u = 0; u < 8; u++) {
            int n0 = g_emem[j + u];
            f[u] = __half22float2(Y2[n0 * 64 + col]);
        }
#pragma unroll
        for (int u = 0; u < 8; u++) { sx += f[u].x; sy += f[u].y; }
    }
    for (; j < end; j++) {
        int n0 = g_emem[j];
        float2 a = __half22float2(Y2[n0 * 64 + col]);
        sx += a.x;
        sy += a.y;
    }
    int cnt = end - beg;
    float inv = 1.f / (float)(cnt > 0 ? cnt : 1);
    ((__half2*)g_emean)[w * 32 + lane] = __floats2half2_rn(sx * inv, sy * inv);
}

// ---------------- K6: per-node output (warp per node) ----------------
// scale-1 slots from g_nmem1; scale-2 slots read directly from sorted hi2 edges.
__global__ void node_out_kernel(const int* __restrict__ hi2, int nnz2,
                                const float* __restrict__ bout, float* __restrict__ out) {
    int w = (blockIdx.x * 256 + threadIdx.x) >> 5;
    int lane = threadIdx.x & 31;
    if (w >= NN) return;
    const __half2* E2 = (const __half2*)g_emean;
    const int* hi2e = hi2 + nnz2;
    float sx = 0.f, sy = 0.f;

    // scale-1 members
    {
        int beg = g_n1ptr[w], end = g_n1ptr[w + 1];
        for (int j = beg; j < end; j++) {
            int e = g_nmem1[j];
            float2 a = __half22float2(E2[e * 32 + lane]);
            sx += a.x;
            sy += a.y;
        }
    }
    // scale-2 members: contiguous run in hi2 (sorted by node)
    {
        int beg = g_n2ptr[w], end = g_n2ptr[w + 1];
        int j = beg;
        for (; j + 8 <= end; j += 8) {
            float2 f[8];
#pragma unroll
            for (int u = 0; u < 8; u++) {
                int e = __ldg(&hi2e[j + u]);
                f[u] = __half22float2(E2[(NE + e) * 32 + lane]);
            }
#pragma unroll
            for (int u = 0; u < 8; u++) { sx += f[u].x; sy += f[u].y; }
        }
        for (; j < end; j++) {
            int e = __ldg(&hi2e[j]);
            float2 a = __half22float2(E2[(NE + e) * 32 + lane]);
            sx += a.x;
            sy += a.y;
        }
    }
    float2 bo = ((const float2*)bout)[lane];
    ((float2*)out)[w * 32 + lane] = make_float2(bo.x + 0.5f * sx, bo.y + 0.5f * sy);
}

// ---------------- launcher ----------------
extern "C" void kernel_launch(void* const* d_in, const int* in_sizes, int n_in,
                              void* d_out, int out_size) {
    const float* x = (const float*)d_in[0];
    const int* hi1 = (const int*)d_in[1];
    const int* hi2 = (const int*)d_in[2];
    const float* W1 = (const float*)d_in[3];
    const float* b1 = (const float*)d_in[4];
    const float* W2 = (const float*)d_in[5];
    const float* b2 = (const float*)d_in[6];
    const float* Wout = (const float*)d_in[7];
    const float* bout = (const float*)d_in[8];
    float* out = (float*)d_out;

    int nnz1 = in_sizes[1] / 2;
    int nnz2 = in_sizes[2] / 2;
    int tot = nnz1 + nnz2;

    init_kernel<<<65 + (NN + 255) / 256, 256>>>(W1, b1, W2, b2, Wout);
    gemmhist_kernel<<<GEMM_BLOCKS + (tot + 255) / 256, 256>>>(x, hi1, hi2, nnz1, nnz2);
    scan_kernel<<<3, 1024>>>();
    int B2 = (nnz2 + 1023) / 1024;  // 4 entries per thread, 256 threads
    fill_kernel<<<B2 + (nnz1 + 255) / 256, 256>>>(hi1, hi2, nnz1, nnz2, B2);
    edge_mean_kernel<<<(2 * NE * 32 + 255) / 256, 256>>>();
    node_out_kernel<<<(NN * 32 + 255) / 256, 256>>>(hi2, nnz2, bout, out);
}

// round 5
// speedup vs baseline: 1.3758x; 1.0002x over previous
#include <cuda_runtime.h>
#include <cuda_fp16.h>

#define NN 10000
#define NE 4000
#define MAXM (4 * 1024 * 1024)

// ---------------- device scratch ----------------
__device__ float g_VT[128 * 128];        // folded weights, transposed
__device__ float g_cc[128];              // folded biases
__device__ __half g_Y[NN * 128];         // fp16 staging
__device__ __half g_emean[2 * NE * 64];  // fp16 staging
__device__ int g_ecnt[2 * NE + 1], g_eptr[2 * NE + 1], g_epos[2 * NE];
__device__ int g_n1cnt[NN + 1], g_n1ptr[NN + 1], g_n1pos[NN];
__device__ int g_n2cnt[NN + 1], g_n2ptr[NN + 1];
__device__ int g_emem[MAXM];     // CSR by edge-slot: member node ids (both scales)
__device__ int g_nmem1[MAXM];    // CSR by node: scale-1 edge ids only (small)

// ---------------- K1: zero histograms + fold weights ----------------
__global__ void init_kernel(const float* __restrict__ W1, const float* __restrict__ b1,
                            const float* __restrict__ W2, const float* __restrict__ b2,
                            const float* __restrict__ Wout) {
    int bb = blockIdx.x;
    if (bb < 64) {
        int idx = bb * 256 + threadIdx.x;
        int j = idx >> 7, k = idx & 127;
        int s = j >> 6, jo = j & 63;
        const float* W = s ? W2 : W1;
        float sum = 0.f;
#pragma unroll 8
        for (int h = 0; h < 128; h++) sum = fmaf(Wout[jo * 128 + h], W[h * 128 + k], sum);
        g_VT[k * 128 + j] = sum;
    } else if (bb == 64) {
        int j = threadIdx.x;
        if (j < 128) {
            int s = j >> 6, jo = j & 63;
            const float* b = s ? b2 : b1;
            float sum = 0.f;
#pragma unroll 8
            for (int h = 0; h < 128; h++) sum = fmaf(Wout[jo * 128 + h], b[h], sum);
            g_cc[j] = sum;
        }
    } else {
        int i = (bb - 65) * 256 + threadIdx.x;
        if (i < 2 * NE) g_ecnt[i] = 0;
        if (i < NN) { g_n1cnt[i] = 0; g_n2cnt[i] = 0; }
    }
}

// ---------------- K2: GEMM (32x128/block) + histogram, fused ----------------
#define GEMM_BLOCKS ((NN + 31) / 32)  // 313

#define FMA4(a, sc, v)                 \
    a.x = fmaf(sc, v.x, a.x);          \
    a.y = fmaf(sc, v.y, a.y);          \
    a.z = fmaf(sc, v.z, a.z);          \
    a.w = fmaf(sc, v.w, a.w);

__global__ __launch_bounds__(256) void gemmhist_kernel(const float* __restrict__ x,
                                                       const int* __restrict__ hi1,
                                                       const int* __restrict__ hi2,
                                                       int nnz1, int nnz2) {
    if (blockIdx.x < GEMM_BLOCKS) {
        int tx = threadIdx.x & 31;
        int ty = threadIdx.x >> 5;
        int row0 = blockIdx.x * 32 + ty * 4;
        const float4* x4 = (const float4*)x;
        const float4* v4 = (const float4*)g_VT;

        int rb0 = (row0 + 0 < NN ? row0 + 0 : NN - 1) * 32;
        int rb1 = (row0 + 1 < NN ? row0 + 1 : NN - 1) * 32;
        int rb2 = (row0 + 2 < NN ? row0 + 2 : NN - 1) * 32;
        int rb3 = (row0 + 3 < NN ? row0 + 3 : NN - 1) * 32;

        float4 a0 = make_float4(0.f, 0.f, 0.f, 0.f), a1 = a0, a2 = a0, a3 = a0;

#pragma unroll 4
        for (int k4 = 0; k4 < 32; k4++) {
            float4 v0 = v4[(4 * k4 + 0) * 32 + tx];
            float4 v1 = v4[(4 * k4 + 1) * 32 + tx];
            float4 v2 = v4[(4 * k4 + 2) * 32 + tx];
            float4 v3 = v4[(4 * k4 + 3) * 32 + tx];
            float4 q;
            q = x4[rb0 + k4];
            FMA4(a0, q.x, v0); FMA4(a0, q.y, v1); FMA4(a0, q.z, v2); FMA4(a0, q.w, v3);
            q = x4[rb1 + k4];
            FMA4(a1, q.x, v0); FMA4(a1, q.y, v1); FMA4(a1, q.z, v2); FMA4(a1, q.w, v3);
            q = x4[rb2 + k4];
            FMA4(a2, q.x, v0); FMA4(a2, q.y, v1); FMA4(a2, q.z, v2); FMA4(a2, q.w, v3);
            q = x4[rb3 + k4];
            FMA4(a3, q.x, v0); FMA4(a3, q.y, v1); FMA4(a3, q.z, v2); FMA4(a3, q.w, v3);
        }
        float4 c = ((const float4*)g_cc)[tx];
        a0.x += c.x; a0.y += c.y; a0.z += c.z; a0.w += c.w;
        a1.x += c.x; a1.y += c.y; a1.z += c.z; a1.w += c.w;
        a2.x += c.x; a2.y += c.y; a2.z += c.z; a2.w += c.w;
        a3.x += c.x; a3.y += c.y; a3.z += c.z; a3.w += c.w;

        union { __half2 h[2]; uint2 u; } cv;
#define STORE_ROW(rr, aa)                                             \
        if (row0 + rr < NN) {                                         \
            cv.h[0] = __floats2half2_rn(aa.x, aa.y);                  \
            cv.h[1] = __floats2half2_rn(aa.z, aa.w);                  \
            ((uint2*)g_Y)[(row0 + rr) * 32 + tx] = cv.u;              \
        }
        STORE_ROW(0, a0) STORE_ROW(1, a1) STORE_ROW(2, a2) STORE_ROW(3, a3)
#undef STORE_ROW
    } else {
        int k = (blockIdx.x - GEMM_BLOCKS) * 256 + threadIdx.x;
        int tot = nnz1 + nnz2;
        if (k >= tot) return;
        if (k < nnz1) {
            int node = __ldg(&hi1[k]), edge = __ldg(&hi1[nnz1 + k]);
            atomicAdd(&g_ecnt[edge], 1);
            atomicAdd(&g_n1cnt[node], 1);
        } else {
            int kk = k - nnz1;
            int node = __ldg(&hi2[kk]), edge = __ldg(&hi2[nnz2 + kk]);
            atomicAdd(&g_ecnt[NE + edge], 1);
            atomicAdd(&g_n2cnt[node], 1);
        }
    }
}

// ---------------- K3: exclusive scans (warp-shuffle) ----------------
__device__ __forceinline__ void block_scan(const int* cnt, int* ptr, int* pos, int n) {
    __shared__ int wsum[32];
    __shared__ int s_tot;
    int t = threadIdx.x, lane = t & 31, wid = t >> 5;
    int carry = 0;
    for (int base = 0; base < n; base += 1024) {
        int i = base + t;
        int v = (i < n) ? cnt[i] : 0;
        int inc = v;
#pragma unroll
        for (int o = 1; o < 32; o <<= 1) {
            int u = __shfl_up_sync(~0u, inc, o);
            if (lane >= o) inc += u;
        }
        if (lane == 31) wsum[wid] = inc;
        __syncthreads();
        if (wid == 0) {
            int w = wsum[lane];
            int wi = w;
#pragma unroll
            for (int o = 1; o < 32; o <<= 1) {
                int u = __shfl_up_sync(~0u, wi, o);
                if (lane >= o) wi += u;
            }
            wsum[lane] = wi - w;
            if (lane == 31) s_tot = wi;
        }
        __syncthreads();
        int excl = carry + wsum[wid] + (inc - v);
        if (i < n) { ptr[i] = excl; if (pos) pos[i] = excl; }
        carry += s_tot;
        __syncthreads();
    }
    if (t == 0) ptr[n] = carry;
}

__global__ void scan_kernel() {
    if (blockIdx.x == 0) block_scan(g_ecnt, g_eptr, g_epos, 2 * NE);
    else if (blockIdx.x == 1) block_scan(g_n1cnt, g_n1ptr, g_n1pos, NN);
    else block_scan(g_n2cnt, g_n2ptr, (int*)0, NN);
}

// ---------------- K4: fill edge-CSR (batched atomics) + scale1 node-CSR ----------------
// blocks [0, B2): scale-2 entries, 4 per thread.  blocks [B2, ...): scale-1 entries.
__global__ __launch_bounds__(256) void fill_kernel(const int* __restrict__ hi1,
                                                   const int* __restrict__ hi2,
                                                   int nnz1, int nnz2, int B2) {
    if (blockIdx.x < B2) {
        int i = (blockIdx.x * 256 + threadIdx.x) * 4;
        if (i >= nnz2) return;
        if (i + 4 <= nnz2) {
            int n0 = __ldg(&hi2[i]),     n1 = __ldg(&hi2[i + 1]);
            int n2 = __ldg(&hi2[i + 2]), n3 = __ldg(&hi2[i + 3]);
            int e0 = __ldg(&hi2[nnz2 + i]),     e1 = __ldg(&hi2[nnz2 + i + 1]);
            int e2 = __ldg(&hi2[nnz2 + i + 2]), e3 = __ldg(&hi2[nnz2 + i + 3]);
            int p0 = atomicAdd(&g_epos[NE + e0], 1);
            int p1 = atomicAdd(&g_epos[NE + e1], 1);
            int p2 = atomicAdd(&g_epos[NE + e2], 1);
            int p3 = atomicAdd(&g_epos[NE + e3], 1);
            g_emem[p0] = n0; g_emem[p1] = n1; g_emem[p2] = n2; g_emem[p3] = n3;
        } else {
            for (int u = i; u < nnz2; u++) {
                int n0 = __ldg(&hi2[u]), e0 = __ldg(&hi2[nnz2 + u]);
                int p = atomicAdd(&g_epos[NE + e0], 1);
                g_emem[p] = n0;
            }
        }
    } else {
        int k = (blockIdx.x - B2) * 256 + threadIdx.x;
        if (k >= nnz1) return;
        int node = __ldg(&hi1[k]), edge = __ldg(&hi1[nnz1 + k]);
        int p = atomicAdd(&g_epos[edge], 1);
        g_emem[p] = node;
        int q = atomicAdd(&g_n1pos[node], 1);
        g_nmem1[q] = edge;
    }
}

// ---------------- K5: per-edge-slot mean (warp per slot) ----------------
__global__ void edge_mean_kernel() {
    int w = (blockIdx.x * 256 + threadIdx.x) >> 5;
    int lane = threadIdx.x & 31;
    if (w >= 2 * NE) return;
    int beg = g_eptr[w], end = g_eptr[w + 1];
    int col = ((w >= NE) ? 32 : 0) + lane;
    const __half2* Y2 = (const __half2*)g_Y;
    float sx = 0.f, sy = 0.f;
    int j = beg;
    for (; j + 8 <= end; j += 8) {
        float2 f[8];
#pragma unroll
        for (int u = 0; u < 8; u++) {
            int n0 = g_emem[j + u];
            f[u] = __half22float2(Y2[n0 * 64 + col]);
        }
#pragma unroll
        for (int u = 0; u < 8; u++) { sx += f[u].x; sy += f[u].y; }
    }
    for (; j < end; j++) {
        int n0 = g_emem[j];
        float2 a = __half22float2(Y2[n0 * 64 + col]);
        sx += a.x;
        sy += a.y;
    }
    int cnt = end - beg;
    float inv = 1.f / (float)(cnt > 0 ? cnt : 1);
    ((__half2*)g_emean)[w * 32 + lane] = __floats2half2_rn(sx * inv, sy * inv);
}

// ---------------- K6: per-node output (warp per node) ----------------
// scale-1 slots from g_nmem1; scale-2 slots read directly from sorted hi2 edges.
__global__ void node_out_kernel(const int* __restrict__ hi2, int nnz2,
                                const float* __restrict__ bout, float* __restrict__ out) {
    int w = (blockIdx.x * 256 + threadIdx.x) >> 5;
    int lane = threadIdx.x & 31;
    if (w >= NN) return;
    const __half2* E2 = (const __half2*)g_emean;
    const int* hi2e = hi2 + nnz2;
    float sx = 0.f, sy = 0.f;

    // scale-1 members
    {
        int beg = g_n1ptr[w], end = g_n1ptr[w + 1];
        for (int j = beg; j < end; j++) {
            int e = g_nmem1[j];
            float2 a = __half22float2(E2[e * 32 + lane]);
            sx += a.x;
            sy += a.y;
        }
    }
    // scale-2 members: contiguous run in hi2 (sorted by node)
    {
        int beg = g_n2ptr[w], end = g_n2ptr[w + 1];
        int j = beg;
        for (; j + 8 <= end; j += 8) {
            float2 f[8];
#pragma unroll
            for (int u = 0; u < 8; u++) {
                int e = __ldg(&hi2e[j + u]);
                f[u] = __half22float2(E2[(NE + e) * 32 + lane]);
            }
#pragma unroll
            for (int u = 0; u < 8; u++) { sx += f[u].x; sy += f[u].y; }
        }
        for (; j < end; j++) {
            int e = __ldg(&hi2e[j]);
            float2 a = __half22float2(E2[(NE + e) * 32 + lane]);
            sx += a.x;
            sy += a.y;
        }
    }
    float2 bo = ((const float2*)bout)[lane];
    ((float2*)out)[w * 32 + lane] = make_float2(bo.x + 0.5f * sx, bo.y + 0.5f * sy);
}

// ---------------- launcher ----------------
extern "C" void kernel_launch(void* const* d_in, const int* in_sizes, int n_in,
                              void* d_out, int out_size) {
    const float* x = (const float*)d_in[0];
    const int* hi1 = (const int*)d_in[1];
    const int* hi2 = (const int*)d_in[2];
    const float* W1 = (const float*)d_in[3];
    const float* b1 = (const float*)d_in[4];
    const float* W2 = (const float*)d_in[5];
    const float* b2 = (const float*)d_in[6];
    const float* Wout = (const float*)d_in[7];
    const float* bout = (const float*)d_in[8];
    float* out = (float*)d_out;

    int nnz1 = in_sizes[1] / 2;
    int nnz2 = in_sizes[2] / 2;
    int tot = nnz1 + nnz2;

    init_kernel<<<65 + (NN + 255) / 256, 256>>>(W1, b1, W2, b2, Wout);
    gemmhist_kernel<<<GEMM_BLOCKS + (tot + 255) / 256, 256>>>(x, hi1, hi2, nnz1, nnz2);
    scan_kernel<<<3, 1024>>>();
    int B2 = (nnz2 + 1023) / 1024;  // 4 entries per thread, 256 threads
    fill_kernel<<<B2 + (nnz1 + 255) / 256, 256>>>(hi1, hi2, nnz1, nnz2, B2);
    edge_mean_kernel<<<(2 * NE * 32 + 255) / 256, 256>>>();
    node_out_kernel<<<(NN * 32 + 255) / 256, 256>>>(hi2, nnz2, bout, out);
}

// round 6
// speedup vs baseline: 1.6985x; 1.2345x over previous
#include <cuda_runtime.h>
#include <cuda_fp16.h>

#define NN 10000
#define NE 4000
#define MAXM (4 * 1024 * 1024)
#define PAD 64  // 256B stride between atomic counters -> spreads across all LTS slices

// ---------------- device scratch ----------------
__device__ float g_VT[128 * 128];
__device__ float g_cc[128];
__device__ __half g_Y[NN * 128];
__device__ __half g_emean[2 * NE * 64];
__device__ int g_ecnt[2 * NE * PAD];      // padded atomic counters (edge hist)
__device__ int g_epos[2 * NE * PAD];      // padded atomic cursors (edge fill)
__device__ int g_eptr[2 * NE + 1];        // compact CSR ptr
__device__ int g_n1cnt[NN * PAD];         // padded (scale-1 node hist)
__device__ int g_n1pos[NN * PAD];         // padded (scale-1 node fill)
__device__ int g_n1ptr[NN + 1];
__device__ int g_n2ptr[NN + 1];           // scale-2 node runs (boundary-detected, no atomics)
__device__ int g_emem[MAXM];
__device__ int g_nmem1[MAXM];

// ---------------- K1: zero counters + default n2ptr + fold weights ----------------
__global__ void init_kernel(const float* __restrict__ W1, const float* __restrict__ b1,
                            const float* __restrict__ W2, const float* __restrict__ b2,
                            const float* __restrict__ Wout, int nnz2) {
    int bb = blockIdx.x;
    if (bb < 64) {
        int idx = bb * 256 + threadIdx.x;
        int j = idx >> 7, k = idx & 127;
        int s = j >> 6, jo = j & 63;
        const float* W = s ? W2 : W1;
        float sum = 0.f;
#pragma unroll 8
        for (int h = 0; h < 128; h++) sum = fmaf(Wout[jo * 128 + h], W[h * 128 + k], sum);
        g_VT[k * 128 + j] = sum;
    } else if (bb == 64) {
        int j = threadIdx.x;
        if (j < 128) {
            int s = j >> 6, jo = j & 63;
            const float* b = s ? b2 : b1;
            float sum = 0.f;
#pragma unroll 8
            for (int h = 0; h < 128; h++) sum = fmaf(Wout[jo * 128 + h], b[h], sum);
            g_cc[j] = sum;
        }
    } else {
        int i = (bb - 65) * 256 + threadIdx.x;
        if (i < 2 * NE) { g_ecnt[i * PAD] = 0; }
        if (i < NN) { g_n1cnt[i * PAD] = 0; }
        if (i <= NN) { g_n2ptr[i] = nnz2; }  // default: covers absent/tail nodes
    }
}

// ---------------- K2: GEMM + padded histogram + n2 run boundaries ----------------
#define GEMM_BLOCKS ((NN + 31) / 32)  // 313

#define FMA4(a, sc, v)                 \
    a.x = fmaf(sc, v.x, a.x);          \
    a.y = fmaf(sc, v.y, a.y);          \
    a.z = fmaf(sc, v.z, a.z);          \
    a.w = fmaf(sc, v.w, a.w);

__global__ __launch_bounds__(256) void gemmhist_kernel(const float* __restrict__ x,
                                                       const int* __restrict__ hi1,
                                                       const int* __restrict__ hi2,
                                                       int nnz1, int nnz2) {
    if (blockIdx.x < GEMM_BLOCKS) {
        int tx = threadIdx.x & 31;
        int ty = threadIdx.x >> 5;
        int row0 = blockIdx.x * 32 + ty * 4;
        const float4* x4 = (const float4*)x;
        const float4* v4 = (const float4*)g_VT;

        int rb0 = (row0 + 0 < NN ? row0 + 0 : NN - 1) * 32;
        int rb1 = (row0 + 1 < NN ? row0 + 1 : NN - 1) * 32;
        int rb2 = (row0 + 2 < NN ? row0 + 2 : NN - 1) * 32;
        int rb3 = (row0 + 3 < NN ? row0 + 3 : NN - 1) * 32;

        float4 a0 = make_float4(0.f, 0.f, 0.f, 0.f), a1 = a0, a2 = a0, a3 = a0;

#pragma unroll 4
        for (int k4 = 0; k4 < 32; k4++) {
            float4 v0 = v4[(4 * k4 + 0) * 32 + tx];
            float4 v1 = v4[(4 * k4 + 1) * 32 + tx];
            float4 v2 = v4[(4 * k4 + 2) * 32 + tx];
            float4 v3 = v4[(4 * k4 + 3) * 32 + tx];
            float4 q;
            q = x4[rb0 + k4];
            FMA4(a0, q.x, v0); FMA4(a0, q.y, v1); FMA4(a0, q.z, v2); FMA4(a0, q.w, v3);
            q = x4[rb1 + k4];
            FMA4(a1, q.x, v0); FMA4(a1, q.y, v1); FMA4(a1, q.z, v2); FMA4(a1, q.w, v3);
            q = x4[rb2 + k4];
            FMA4(a2, q.x, v0); FMA4(a2, q.y, v1); FMA4(a2, q.z, v2); FMA4(a2, q.w, v3);
            q = x4[rb3 + k4];
            FMA4(a3, q.x, v0); FMA4(a3, q.y, v1); FMA4(a3, q.z, v2); FMA4(a3, q.w, v3);
        }
        float4 c = ((const float4*)g_cc)[tx];
        a0.x += c.x; a0.y += c.y; a0.z += c.z; a0.w += c.w;
        a1.x += c.x; a1.y += c.y; a1.z += c.z; a1.w += c.w;
        a2.x += c.x; a2.y += c.y; a2.z += c.z; a2.w += c.w;
        a3.x += c.x; a3.y += c.y; a3.z += c.z; a3.w += c.w;

        union { __half2 h[2]; uint2 u; } cv;
#define STORE_ROW(rr, aa)                                             \
        if (row0 + rr < NN) {                                         \
            cv.h[0] = __floats2half2_rn(aa.x, aa.y);                  \
            cv.h[1] = __floats2half2_rn(aa.z, aa.w);                  \
            ((uint2*)g_Y)[(row0 + rr) * 32 + tx] = cv.u;              \
        }
        STORE_ROW(0, a0) STORE_ROW(1, a1) STORE_ROW(2, a2) STORE_ROW(3, a3)
#undef STORE_ROW
    } else {
        int k = (blockIdx.x - GEMM_BLOCKS) * 256 + threadIdx.x;
        int tot = nnz1 + nnz2;
        if (k >= tot) return;
        if (k < nnz1) {
            int node = __ldg(&hi1[k]), edge = __ldg(&hi1[nnz1 + k]);
            atomicAdd(&g_ecnt[edge * PAD], 1);
            atomicAdd(&g_n1cnt[node * PAD], 1);
        } else {
            int kk = k - nnz1;
            int edge = __ldg(&hi2[nnz2 + kk]);
            atomicAdd(&g_ecnt[(NE + edge) * PAD], 1);
            // scale-2 node runs via boundary detection (hi2 sorted by node)
            int node = __ldg(&hi2[kk]);
            int prev = (kk == 0) ? -1 : __ldg(&hi2[kk - 1]);
            if (node != prev) {
                for (int n = prev + 1; n <= node; n++) g_n2ptr[n] = kk;
            }
        }
    }
}

// ---------------- K3: exclusive scans over strided counters ----------------
__device__ __forceinline__ void block_scan(const int* cnt, int* ptr, int* pos, int n) {
    __shared__ int wsum[32];
    __shared__ int s_tot;
    int t = threadIdx.x, lane = t & 31, wid = t >> 5;
    int carry = 0;
    for (int base = 0; base < n; base += 1024) {
        int i = base + t;
        int v = (i < n) ? cnt[i * PAD] : 0;
        int inc = v;
#pragma unroll
        for (int o = 1; o < 32; o <<= 1) {
            int u = __shfl_up_sync(~0u, inc, o);
            if (lane >= o) inc += u;
        }
        if (lane == 31) wsum[wid] = inc;
        __syncthreads();
        if (wid == 0) {
            int w = wsum[lane];
            int wi = w;
#pragma unroll
            for (int o = 1; o < 32; o <<= 1) {
                int u = __shfl_up_sync(~0u, wi, o);
                if (lane >= o) wi += u;
            }
            wsum[lane] = wi - w;
            if (lane == 31) s_tot = wi;
        }
        __syncthreads();
        int excl = carry + wsum[wid] + (inc - v);
        if (i < n) { ptr[i] = excl; pos[i * PAD] = excl; }
        carry += s_tot;
        __syncthreads();
    }
    if (t == 0) ptr[n] = carry;
}

__global__ void scan_kernel() {
    if (blockIdx.x == 0) block_scan(g_ecnt, g_eptr, g_epos, 2 * NE);
    else block_scan(g_n1cnt, g_n1ptr, g_n1pos, NN);
}

// ---------------- K4: fill edge-CSR (padded atomics) + scale1 node-CSR ----------------
__global__ __launch_bounds__(256) void fill_kernel(const int* __restrict__ hi1,
                                                   const int* __restrict__ hi2,
                                                   int nnz1, int nnz2, int B2) {
    if (blockIdx.x < B2) {
        int i = (blockIdx.x * 256 + threadIdx.x) * 4;
        if (i >= nnz2) return;
        if (i + 4 <= nnz2) {
            int n0 = __ldg(&hi2[i]),     n1 = __ldg(&hi2[i + 1]);
            int n2 = __ldg(&hi2[i + 2]), n3 = __ldg(&hi2[i + 3]);
            int e0 = __ldg(&hi2[nnz2 + i]),     e1 = __ldg(&hi2[nnz2 + i + 1]);
            int e2 = __ldg(&hi2[nnz2 + i + 2]), e3 = __ldg(&hi2[nnz2 + i + 3]);
            int p0 = atomicAdd(&g_epos[(NE + e0) * PAD], 1);
            int p1 = atomicAdd(&g_epos[(NE + e1) * PAD], 1);
            int p2 = atomicAdd(&g_epos[(NE + e2) * PAD], 1);
            int p3 = atomicAdd(&g_epos[(NE + e3) * PAD], 1);
            g_emem[p0] = n0; g_emem[p1] = n1; g_emem[p2] = n2; g_emem[p3] = n3;
        } else {
            for (int u = i; u < nnz2; u++) {
                int n0 = __ldg(&hi2[u]), e0 = __ldg(&hi2[nnz2 + u]);
                int p = atomicAdd(&g_epos[(NE + e0) * PAD], 1);
                g_emem[p] = n0;
            }
        }
    } else {
        int k = (blockIdx.x - B2) * 256 + threadIdx.x;
        if (k >= nnz1) return;
        int node = __ldg(&hi1[k]), edge = __ldg(&hi1[nnz1 + k]);
        int p = atomicAdd(&g_epos[edge * PAD], 1);
        g_emem[p] = node;
        int q = atomicAdd(&g_n1pos[node * PAD], 1);
        g_nmem1[q] = edge;
    }
}

// ---------------- K5: per-edge-slot mean (warp per slot) ----------------
__global__ void edge_mean_kernel() {
    int w = (blockIdx.x * 256 + threadIdx.x) >> 5;
    int lane = threadIdx.x & 31;
    if (w >= 2 * NE) return;
    int beg = g_eptr[w], end = g_eptr[w + 1];
    int col = ((w >= NE) ? 32 : 0) + lane;
    const __half2* Y2 = (const __half2*)g_Y;
    float sx = 0.f, sy = 0.f;
    int j = beg;
    for (; j + 8 <= end; j += 8) {
        float2 f[8];
#pragma unroll
        for (int u = 0; u < 8; u++) {
            int n0 = g_emem[j + u];
            f[u] = __half22float2(Y2[n0 * 64 + col]);
        }
#pragma unroll
        for (int u = 0; u < 8; u++) { sx += f[u].x; sy += f[u].y; }
    }
    for (; j < end; j++) {
        int n0 = g_emem[j];
        float2 a = __half22float2(Y2[n0 * 64 + col]);
        sx += a.x;
        sy += a.y;
    }
    int cnt = end - beg;
    float inv = 1.f / (float)(cnt > 0 ? cnt : 1);
    ((__half2*)g_emean)[w * 32 + lane] = __floats2half2_rn(sx * inv, sy * inv);
}

// ---------------- K6: per-node output (warp per node) ----------------
__global__ void node_out_kernel(const int* __restrict__ hi2, int nnz2,
                                const float* __restrict__ bout, float* __restrict__ out) {
    int w = (blockIdx.x * 256 + threadIdx.x) >> 5;
    int lane = threadIdx.x & 31;
    if (w >= NN) return;
    const __half2* E2 = (const __half2*)g_emean;
    const int* hi2e = hi2 + nnz2;
    float sx = 0.f, sy = 0.f;

    {
        int beg = g_n1ptr[w], end = g_n1ptr[w + 1];
        for (int j = beg; j < end; j++) {
            int e = g_nmem1[j];
            float2 a = __half22float2(E2[e * 32 + lane]);
            sx += a.x;
            sy += a.y;
        }
    }
    {
        int beg = g_n2ptr[w], end = g_n2ptr[w + 1];
        int j = beg;
        for (; j + 8 <= end; j += 8) {
            float2 f[8];
#pragma unroll
            for (int u = 0; u < 8; u++) {
                int e = __ldg(&hi2e[j + u]);
                f[u] = __half22float2(E2[(NE + e) * 32 + lane]);
            }
#pragma unroll
            for (int u = 0; u < 8; u++) { sx += f[u].x; sy += f[u].y; }
        }
        for (; j < end; j++) {
            int e = __ldg(&hi2e[j]);
            float2 a = __half22float2(E2[(NE + e) * 32 + lane]);
            sx += a.x;
            sy += a.y;
        }
    }
    float2 bo = ((const float2*)bout)[lane];
    ((float2*)out)[w * 32 + lane] = make_float2(bo.x + 0.5f * sx, bo.y + 0.5f * sy);
}

// ---------------- launcher ----------------
extern "C" void kernel_launch(void* const* d_in, const int* in_sizes, int n_in,
                              void* d_out, int out_size) {
    const float* x = (const float*)d_in[0];
    const int* hi1 = (const int*)d_in[1];
    const int* hi2 = (const int*)d_in[2];
    const float* W1 = (const float*)d_in[3];
    const float* b1 = (const float*)d_in[4];
    const float* W2 = (const float*)d_in[5];
    const float* b2 = (const float*)d_in[6];
    const float* Wout = (const float*)d_in[7];
    const float* bout = (const float*)d_in[8];
    float* out = (float*)d_out;

    int nnz1 = in_sizes[1] / 2;
    int nnz2 = in_sizes[2] / 2;
    int tot = nnz1 + nnz2;

    init_kernel<<<65 + (NN + 255) / 256, 256>>>(W1, b1, W2, b2, Wout, nnz2);
    gemmhist_kernel<<<GEMM_BLOCKS + (tot + 255) / 256, 256>>>(x, hi1, hi2, nnz1, nnz2);
    scan_kernel<<<2, 1024>>>();
    int B2 = (nnz2 + 1023) / 1024;
    fill_kernel<<<B2 + (nnz1 + 255) / 256, 256>>>(hi1, hi2, nnz1, nnz2, B2);
    edge_mean_kernel<<<(2 * NE * 32 + 255) / 256, 256>>>();
    node_out_kernel<<<(NN * 32 + 255) / 256, 256>>>(hi2, nnz2, bout, out);
}